// round 1
// baseline (speedup 1.0000x reference)
#include <cuda_runtime.h>
#include <math.h>

#define B_ 4
#define S_ 2048
#define T_ 8192   // B_*S_
#define D_ 1024
#define H_ 4096
#define E_ 8

// ---------------- static device scratch (no allocations allowed) ----------------
__device__ float g_w1s[E_ * H_];          // g/||v|| for layer1 rows
__device__ float g_w2s[E_ * D_];          // g/||v|| for layer2 rows
__device__ float g_gs[E_];                // g/||v|| for gate rows
__device__ int   g_cnt[E_];               // per-expert token counts
__device__ int   g_tok[E_ * T_];          // per-expert token lists
__device__ int   g_assign[T_ * 2];        // token -> 2 assignment ids (e*T_+slot), expert-sorted
__device__ float g_hidden[(size_t)E_ * T_ * H_];   // swish(h) per assignment
__device__ float g_partial[(size_t)E_ * T_ * D_];  // per-assignment layer2 output

// ---------------- small utility kernels ----------------
__global__ void zero_counts_kernel() {
    if (threadIdx.x < E_) g_cnt[threadIdx.x] = 0;
}

// one warp per row: scale = g / max(||v_row||, 1e-12)
__global__ void rownorm_kernel(const float* __restrict__ v,
                               const float* __restrict__ g,
                               int which, int rows, int K)
{
    int row = (blockIdx.x * blockDim.x + threadIdx.x) >> 5;
    if (row >= rows) return;
    int lane = threadIdx.x & 31;
    const float4* p = (const float4*)(v + (size_t)row * K);
    float s = 0.f;
    int n4 = K >> 2;
    for (int i = lane; i < n4; i += 32) {
        float4 a = p[i];
        s += a.x * a.x + a.y * a.y + a.z * a.z + a.w * a.w;
    }
    #pragma unroll
    for (int o = 16; o; o >>= 1) s += __shfl_xor_sync(0xffffffffu, s, o);
    if (lane == 0) {
        float* out = (which == 0) ? g_w1s : (which == 1) ? g_w2s : g_gs;
        out[row] = g[row] / fmaxf(sqrtf(s), 1e-12f);
    }
}

// one warp per token: 8 gate logits, top-2, compact into expert lists
__global__ void route_kernel(const float* __restrict__ x,
                             const float* __restrict__ gate_v,
                             const float* __restrict__ gate_b)
{
    int t = (blockIdx.x * blockDim.x + threadIdx.x) >> 5;
    if (t >= T_) return;
    int lane = threadIdx.x & 31;

    const float4* xp = (const float4*)(x + (size_t)t * D_);
    float4 xr[8];
    #pragma unroll
    for (int i = 0; i < 8; i++) xr[i] = xp[lane + 32 * i];

    float logit[E_];
    #pragma unroll
    for (int e = 0; e < E_; e++) {
        const float4* gp = (const float4*)(gate_v + (size_t)e * D_);
        float s = 0.f;
        #pragma unroll
        for (int i = 0; i < 8; i++) {
            float4 g4 = gp[lane + 32 * i];
            s += xr[i].x * g4.x + xr[i].y * g4.y + xr[i].z * g4.z + xr[i].w * g4.w;
        }
        #pragma unroll
        for (int o = 16; o; o >>= 1) s += __shfl_xor_sync(0xffffffffu, s, o);
        logit[e] = s;
    }

    if (lane == 0) {
        // softmax is monotonic -> top-2 of logits; strict '>' keeps lower index on ties (jax top_k order)
        int b0 = -1, b1i = -1;
        float v0 = -1e30f, v1 = -1e30f;
        #pragma unroll
        for (int e = 0; e < E_; e++) {
            float l = logit[e] * g_gs[e] + gate_b[e];
            if (l > v0)      { v1 = v0; b1i = b0; v0 = l; b0 = e; }
            else if (l > v1) { v1 = l; b1i = e; }
        }
        int e0 = min(b0, b1i), e1 = max(b0, b1i);
        int s0 = atomicAdd(&g_cnt[e0], 1);
        g_tok[e0 * T_ + s0] = t;
        g_assign[2 * t] = e0 * T_ + s0;
        int s1 = atomicAdd(&g_cnt[e1], 1);
        g_tok[e1 * T_ + s1] = t;
        g_assign[2 * t + 1] = e1 * T_ + s1;
    }
}

// ---------------- tiled SGEMM (128x128xK, BK=8, 256 thr, 8x8/thread, double-buffered) ----------------
// FIRST=true : C = gather(x) @ w1_v[e]^T ; epilogue: swish(z*scale1 + b1) -> g_hidden
// FIRST=false: C = hidden[e] @ w2_v[e]^T ; epilogue: z*scale2 + b2       -> g_partial
template <int K, bool FIRST>
__global__ __launch_bounds__(256) void gemm_kernel(const float* __restrict__ x,
                                                   const float* __restrict__ W,
                                                   const float* __restrict__ bias)
{
    const int e   = blockIdx.z;
    const int cnt = g_cnt[e];
    const int m0  = blockIdx.y * 128;
    if (m0 >= cnt) return;
    const int n0  = blockIdx.x * 128;
    constexpr int N_TOT = FIRST ? H_ : D_;

    __shared__ float As[2][8][128];
    __shared__ float Bs[2][8][128];
    __shared__ const float* Arows[128];

    const int tid = threadIdx.x;
    if (tid < 128) {
        int m = m0 + tid;
        if (m >= cnt) m = cnt - 1;   // duplicate last valid row; results discarded below
        const float* p;
        if (FIRST) p = x + (size_t)g_tok[e * T_ + m] * K;
        else       p = g_hidden + ((size_t)(e * T_) + m) * K;
        Arows[tid] = p;
    }
    __syncthreads();

    const int ar = tid >> 1;
    const int ak = (tid & 1) * 4;
    const float* Aptr = Arows[ar] + ak;
    const float* Bptr = W + (size_t)e * N_TOT * K + (size_t)(n0 + ar) * K + ak;

    // prologue: stage k-tile 0
    {
        float4 av = *(const float4*)Aptr;
        float4 bv = *(const float4*)Bptr;
        #pragma unroll
        for (int j = 0; j < 4; j++) {
            As[0][ak + j][ar] = ((const float*)&av)[j];
            Bs[0][ak + j][ar] = ((const float*)&bv)[j];
        }
    }
    __syncthreads();

    const int tm = (tid >> 4) << 3;
    const int tn = (tid & 15) << 3;
    float acc[8][8] = {};

    int buf = 0;
    for (int k0 = 8; k0 <= K; k0 += 8) {
        float4 an, bn;
        if (k0 < K) {
            an = *(const float4*)(Aptr + k0);
            bn = *(const float4*)(Bptr + k0);
        }
        #pragma unroll
        for (int kk = 0; kk < 8; kk++) {
            float4 a0 = *(const float4*)&As[buf][kk][tm];
            float4 a1 = *(const float4*)&As[buf][kk][tm + 4];
            float4 b0 = *(const float4*)&Bs[buf][kk][tn];
            float4 b1v = *(const float4*)&Bs[buf][kk][tn + 4];
            float a[8] = {a0.x, a0.y, a0.z, a0.w, a1.x, a1.y, a1.z, a1.w};
            float b[8] = {b0.x, b0.y, b0.z, b0.w, b1v.x, b1v.y, b1v.z, b1v.w};
            #pragma unroll
            for (int i = 0; i < 8; i++)
                #pragma unroll
                for (int j = 0; j < 8; j++)
                    acc[i][j] += a[i] * b[j];
        }
        if (k0 < K) {
            buf ^= 1;
            #pragma unroll
            for (int j = 0; j < 4; j++) {
                As[buf][ak + j][ar] = ((const float*)&an)[j];
                Bs[buf][ak + j][ar] = ((const float*)&bn)[j];
            }
            __syncthreads();
        }
    }

    // epilogue: fold weight-norm scale + bias (+ swish for layer1)
    float scl[8], bs[8];
    #pragma unroll
    for (int j = 0; j < 8; j++) {
        int n = n0 + tn + j;
        scl[j] = FIRST ? g_w1s[e * H_ + n] : g_w2s[e * D_ + n];
        bs[j]  = bias[e * N_TOT + n];
    }
    #pragma unroll
    for (int i = 0; i < 8; i++) {
        int m = m0 + tm + i;
        if (m < cnt) {
            float* orow;
            if (FIRST) orow = g_hidden + ((size_t)(e * T_) + m) * H_ + n0 + tn;
            else       orow = g_partial + ((size_t)(e * T_) + m) * D_ + n0 + tn;
            float tmp[8];
            #pragma unroll
            for (int j = 0; j < 8; j++) {
                float z = acc[i][j] * scl[j] + bs[j];
                tmp[j] = FIRST ? (z / (1.f + expf(-z))) : z;   // swish for layer1
            }
            *(float4*)(orow)     = *(const float4*)(tmp);
            *(float4*)(orow + 4) = *(const float4*)(tmp + 4);
        }
    }
}

// out[t] = partial[a0] + partial[a1] (fixed expert-sorted order -> deterministic)
__global__ void sum_kernel(float* __restrict__ out) {
    int t = blockIdx.x;
    int a0 = g_assign[2 * t], a1 = g_assign[2 * t + 1];
    const float4* p0 = (const float4*)(g_partial + (size_t)a0 * D_);
    const float4* p1 = (const float4*)(g_partial + (size_t)a1 * D_);
    float4* o = (float4*)(out + (size_t)t * D_);
    int i = threadIdx.x;   // 256 threads * float4 = 1024 floats = D_
    float4 u = p0[i], w = p1[i];
    o[i] = make_float4(u.x + w.x, u.y + w.y, u.z + w.z, u.w + w.w);
}

// ---------------- launch ----------------
extern "C" void kernel_launch(void* const* d_in, const int* in_sizes, int n_in,
                              void* d_out, int out_size)
{
    const float* x      = (const float*)d_in[0];
    const float* gate_v = (const float*)d_in[1];
    const float* gate_g = (const float*)d_in[2];
    const float* gate_b = (const float*)d_in[3];
    const float* w1_v   = (const float*)d_in[4];
    const float* w1_g   = (const float*)d_in[5];
    const float* b1     = (const float*)d_in[6];
    const float* w2_v   = (const float*)d_in[7];
    const float* w2_g   = (const float*)d_in[8];
    const float* b2     = (const float*)d_in[9];
    float* out = (float*)d_out;

    zero_counts_kernel<<<1, 32>>>();

    // weight-norm scales: one warp per row
    rownorm_kernel<<<(E_ * H_) / 8, 256>>>(w1_v, w1_g, 0, E_ * H_, D_);   // 4096 blocks
    rownorm_kernel<<<(E_ * D_) / 8, 256>>>(w2_v, w2_g, 1, E_ * D_, H_);   // 1024 blocks
    rownorm_kernel<<<1, 256>>>(gate_v, gate_g, 2, E_, D_);

    route_kernel<<<T_ / 8, 256>>>(x, gate_v, gate_b);

    // layer1: [cnt_e,1024] @ [1024,4096]^T, gathered rows of x
    gemm_kernel<D_, true><<<dim3(H_ / 128, T_ / 128, E_), 256>>>(x, w1_v, b1);
    // layer2: [cnt_e,4096] @ [4096,1024]^T
    gemm_kernel<H_, false><<<dim3(D_ / 128, T_ / 128, E_), 256>>>(nullptr, w2_v, b2);

    sum_kernel<<<T_, 256>>>(out);
}

// round 3
// speedup vs baseline: 2.5267x; 2.5267x over previous
#include <cuda_runtime.h>
#include <cuda_bf16.h>
#include <math.h>
#include <stdint.h>

#define T_ 8192
#define D_ 1024
#define H_ 4096
#define E_ 8

#define BM 128
#define BN 128
#define BK 32
#define NT 256
#define STAGES 4
#define TILE_B (128 * 64)            // one 128x32 bf16 tile = 8192 bytes
#define STAGE_B (4 * TILE_B)         // Ahi,Alo,Bhi,Blo = 32768
#define SMEM_DYN (STAGES * STAGE_B)  // 131072

// ---------------- static device scratch ----------------
__device__ float g_gs[E_];
__device__ int   g_cnt[E_];
__device__ int   g_assign[T_ * 2];
__device__ __nv_bfloat16 g_xg_hi[(size_t)E_ * T_ * D_];
__device__ __nv_bfloat16 g_xg_lo[(size_t)E_ * T_ * D_];
__device__ __nv_bfloat16 g_w1_hi[(size_t)E_ * H_ * D_];
__device__ __nv_bfloat16 g_w1_lo[(size_t)E_ * H_ * D_];
__device__ __nv_bfloat16 g_w2_hi[(size_t)E_ * D_ * H_];
__device__ __nv_bfloat16 g_w2_lo[(size_t)E_ * D_ * H_];
__device__ __nv_bfloat16 g_h_hi[(size_t)E_ * T_ * H_];
__device__ __nv_bfloat16 g_h_lo[(size_t)E_ * T_ * H_];
__device__ float g_partial[(size_t)E_ * T_ * D_];

// ---------------- PTX helpers (all legal on generic sm_103 target) ----------------
__device__ __forceinline__ uint32_t s2u(const void* p) {
    uint32_t a;
    asm("{ .reg .u64 t; cvta.to.shared.u64 t, %1; cvt.u32.u64 %0, t; }" : "=r"(a) : "l"(p));
    return a;
}
__device__ __forceinline__ void cpa16(uint32_t dst, const void* src) {
    asm volatile("cp.async.cg.shared.global [%0], [%1], 16;\n" :: "r"(dst), "l"(src) : "memory");
}
__device__ __forceinline__ void cpa_commit() { asm volatile("cp.async.commit_group;\n" ::: "memory"); }
template <int N> __device__ __forceinline__ void cpa_wait() {
    asm volatile("cp.async.wait_group %0;\n" :: "n"(N) : "memory");
}
__device__ __forceinline__ void ldsm_x4(uint32_t a, uint32_t& r0, uint32_t& r1, uint32_t& r2, uint32_t& r3) {
    asm volatile("ldmatrix.sync.aligned.m8n8.x4.shared.b16 {%0,%1,%2,%3}, [%4];"
                 : "=r"(r0), "=r"(r1), "=r"(r2), "=r"(r3) : "r"(a));
}
__device__ __forceinline__ void ldsm_x2(uint32_t a, uint32_t& r0, uint32_t& r1) {
    asm volatile("ldmatrix.sync.aligned.m8n8.x2.shared.b16 {%0,%1}, [%2];"
                 : "=r"(r0), "=r"(r1) : "r"(a));
}
__device__ __forceinline__ void mma_bf16(float* d, const uint32_t* a, const uint32_t* b) {
    asm volatile("mma.sync.aligned.m16n8k16.row.col.f32.bf16.bf16.f32 "
                 "{%0,%1,%2,%3}, {%4,%5,%6,%7}, {%8,%9}, {%0,%1,%2,%3};"
                 : "+f"(d[0]), "+f"(d[1]), "+f"(d[2]), "+f"(d[3])
                 : "r"(a[0]), "r"(a[1]), "r"(a[2]), "r"(a[3]), "r"(b[0]), "r"(b[1]));
}
__device__ __forceinline__ void split2(float x, unsigned short& h, unsigned short& l) {
    __nv_bfloat16 hb = __float2bfloat16(x);
    __nv_bfloat16 lb = __float2bfloat16(x - __bfloat162float(hb));
    h = __bfloat16_as_ushort(hb);
    l = __bfloat16_as_ushort(lb);
}
// swizzled byte offset inside a 128x32 bf16 tile (rows of 64B, 16B chunks)
__device__ __forceinline__ uint32_t sw_off(int r, int c) {
    return (uint32_t)(r * 64 + ((c ^ ((r >> 1) & 3)) << 4));
}

// ---------------- small kernels ----------------
__global__ void zero_counts_kernel() {
    if (threadIdx.x < E_) g_cnt[threadIdx.x] = 0;
}

__global__ void gate_norm_kernel(const float* __restrict__ gv, const float* __restrict__ gg) {
    int row = threadIdx.x >> 5;
    if (row >= E_) return;
    int lane = threadIdx.x & 31;
    const float4* p = (const float4*)(gv + (size_t)row * D_);
    float s = 0.f;
    for (int i = lane; i < D_ / 4; i += 32) {
        float4 a = p[i];
        s += a.x * a.x + a.y * a.y + a.z * a.z + a.w * a.w;
    }
    #pragma unroll
    for (int o = 16; o; o >>= 1) s += __shfl_xor_sync(0xffffffffu, s, o);
    if (lane == 0) g_gs[row] = gg[row] / fmaxf(sqrtf(s), 1e-12f);
}

// one warp per token: 8 gate logits, top-2, compact into expert slot lists
__global__ void route_kernel(const float* __restrict__ x,
                             const float* __restrict__ gate_v,
                             const float* __restrict__ gate_b)
{
    int t = (blockIdx.x * blockDim.x + threadIdx.x) >> 5;
    if (t >= T_) return;
    int lane = threadIdx.x & 31;
    const float4* xp = (const float4*)(x + (size_t)t * D_);
    float4 xr[8];
    #pragma unroll
    for (int i = 0; i < 8; i++) xr[i] = xp[lane + 32 * i];
    float logit[E_];
    #pragma unroll
    for (int e = 0; e < E_; e++) {
        const float4* gp = (const float4*)(gate_v + (size_t)e * D_);
        float s = 0.f;
        #pragma unroll
        for (int i = 0; i < 8; i++) {
            float4 g4 = gp[lane + 32 * i];
            s += xr[i].x * g4.x + xr[i].y * g4.y + xr[i].z * g4.z + xr[i].w * g4.w;
        }
        #pragma unroll
        for (int o = 16; o; o >>= 1) s += __shfl_xor_sync(0xffffffffu, s, o);
        logit[e] = s;
    }
    if (lane == 0) {
        int b0 = -1, b1i = -1;
        float v0 = -1e30f, v1 = -1e30f;
        #pragma unroll
        for (int e = 0; e < E_; e++) {
            float l = logit[e] * g_gs[e] + gate_b[e];
            if (l > v0)      { v1 = v0; b1i = b0; v0 = l; b0 = e; }
            else if (l > v1) { v1 = l; b1i = e; }
        }
        int e0 = min(b0, b1i), e1 = max(b0, b1i);
        int s0 = atomicAdd(&g_cnt[e0], 1);
        g_assign[2 * t] = e0 * T_ + s0;
        int s1 = atomicAdd(&g_cnt[e1], 1);
        g_assign[2 * t + 1] = e1 * T_ + s1;
    }
}

// gather x rows into assignment slots, split hi/lo bf16
__global__ void gather_kernel(const float* __restrict__ x) {
    int t = blockIdx.x;
    int i = threadIdx.x;   // 256 threads * float4 = 1024
    float4 v = ((const float4*)(x + (size_t)t * D_))[i];
    float f[4] = {v.x, v.y, v.z, v.w};
    unsigned short h[4], l[4];
    #pragma unroll
    for (int j = 0; j < 4; j++) split2(f[j], h[j], l[j]);
    uint2 hp, lp;
    hp.x = (uint32_t)h[0] | ((uint32_t)h[1] << 16);
    hp.y = (uint32_t)h[2] | ((uint32_t)h[3] << 16);
    lp.x = (uint32_t)l[0] | ((uint32_t)l[1] << 16);
    lp.y = (uint32_t)l[2] | ((uint32_t)l[3] << 16);
    int a0 = g_assign[2 * t], a1 = g_assign[2 * t + 1];
    ((uint2*)(g_xg_hi + (size_t)a0 * D_))[i] = hp;
    ((uint2*)(g_xg_lo + (size_t)a0 * D_))[i] = lp;
    ((uint2*)(g_xg_hi + (size_t)a1 * D_))[i] = hp;
    ((uint2*)(g_xg_lo + (size_t)a1 * D_))[i] = lp;
}

// fused weight-norm + scale-fold + hi/lo split. which=0 -> w1, which=1 -> w2
__global__ void wconv_kernel(const float* __restrict__ v, const float* __restrict__ g,
                             int which, int K)
{
    int row = (blockIdx.x * blockDim.x + threadIdx.x) >> 5;
    int lane = threadIdx.x & 31;
    const float4* p = (const float4*)(v + (size_t)row * K);
    float s = 0.f;
    int n4 = K >> 2;
    for (int i = lane; i < n4; i += 32) {
        float4 a = p[i];
        s += a.x * a.x + a.y * a.y + a.z * a.z + a.w * a.w;
    }
    #pragma unroll
    for (int o = 16; o; o >>= 1) s += __shfl_xor_sync(0xffffffffu, s, o);
    float scl = g[row] / fmaxf(sqrtf(s), 1e-12f);
    __nv_bfloat16* whi = which ? g_w2_hi : g_w1_hi;
    __nv_bfloat16* wlo = which ? g_w2_lo : g_w1_lo;
    uint2* oh = (uint2*)(whi + (size_t)row * K);
    uint2* ol = (uint2*)(wlo + (size_t)row * K);
    for (int i = lane; i < n4; i += 32) {
        float4 a = p[i];
        float f[4] = {a.x * scl, a.y * scl, a.z * scl, a.w * scl};
        unsigned short h[4], l[4];
        #pragma unroll
        for (int j = 0; j < 4; j++) split2(f[j], h[j], l[j]);
        uint2 hp, lp;
        hp.x = (uint32_t)h[0] | ((uint32_t)h[1] << 16);
        hp.y = (uint32_t)h[2] | ((uint32_t)h[3] << 16);
        lp.x = (uint32_t)l[0] | ((uint32_t)l[1] << 16);
        lp.y = (uint32_t)l[2] | ((uint32_t)l[3] << 16);
        oh[i] = hp;
        ol[i] = lp;
    }
}

// ---------------- split-bf16 HMMA GEMM (mma.sync m16n8k16) ----------------
// FIRST: [cnt,1024] @ w1^T -> swish -> g_h (hi/lo bf16)
// else : [cnt,4096] @ w2^T -> + b2  -> g_partial (fp32)
template <int K, bool FIRST>
__global__ __launch_bounds__(NT, 1) void gemm_kernel(const float* __restrict__ bias)
{
    const int e   = blockIdx.z;
    const int cnt = g_cnt[e];
    const int m0  = blockIdx.y * BM;
    if (m0 >= cnt) return;
    const int n0  = blockIdx.x * BN;
    constexpr int NTOT = FIRST ? H_ : D_;
    constexpr int NC = K / BK;

    extern __shared__ char smem_raw[];
    const uint32_t sbase = s2u(smem_raw);
    const int tid  = threadIdx.x;
    const int lane = tid & 31;
    const int wid  = tid >> 5;
    const int wm   = (wid & 1) * 64;   // warp m offset in tile
    const int wn   = (wid >> 1) * 32;  // warp n offset in tile

    const size_t arow = (size_t)(e * T_ + m0);
    const __nv_bfloat16* Ahi_g = (FIRST ? g_xg_hi : g_h_hi) + arow * K;
    const __nv_bfloat16* Alo_g = (FIRST ? g_xg_lo : g_h_lo) + arow * K;
    const __nv_bfloat16* Bhi_g = (FIRST ? g_w1_hi : g_w2_hi) + ((size_t)e * NTOT + n0) * K;
    const __nv_bfloat16* Blo_g = (FIRST ? g_w1_lo : g_w2_lo) + ((size_t)e * NTOT + n0) * K;

    auto load_chunk = [&](int c, int s) {
        uint32_t stg = sbase + s * STAGE_B;
        #pragma unroll
        for (int q = 0; q < 8; q++) {
            int i   = tid + q * NT;       // 0..2047
            int mtx = i >> 9;             // 0 Ahi 1 Alo 2 Bhi 3 Blo
            int r   = (i >> 2) & 127;
            int cc  = i & 3;
            const __nv_bfloat16* src =
                (mtx == 0) ? Ahi_g : (mtx == 1) ? Alo_g : (mtx == 2) ? Bhi_g : Blo_g;
            src += (size_t)r * K + c * BK + cc * 8;
            cpa16(stg + mtx * TILE_B + sw_off(r, cc), src);
        }
    };

    float acc[4][4][4] = {};

    // prologue: stage first 3 chunks
    #pragma unroll
    for (int c = 0; c < STAGES - 1; ++c) { load_chunk(c, c); cpa_commit(); }

    for (int c = 0; c < NC; ++c) {
        const int s = c & (STAGES - 1);
        cpa_wait<STAGES - 2>();
        __syncthreads();
        const int cn = c + STAGES - 1;
        if (cn < NC) load_chunk(cn, cn & (STAGES - 1));
        cpa_commit();

        const uint32_t sAh = sbase + s * STAGE_B;
        const uint32_t sAl = sAh + TILE_B;
        const uint32_t sBh = sAh + 2 * TILE_B;
        const uint32_t sBl = sAh + 3 * TILE_B;

        #pragma unroll
        for (int ks = 0; ks < 2; ++ks) {
            uint32_t ah[4][4], al[4][4], bh[4][2], bl[4][2];
            const int ar = lane & 15;
            const int ac = ks * 2 + (lane >> 4);
            #pragma unroll
            for (int im = 0; im < 4; im++) {
                uint32_t off = sw_off(wm + im * 16 + ar, ac);
                ldsm_x4(sAh + off, ah[im][0], ah[im][1], ah[im][2], ah[im][3]);
                ldsm_x4(sAl + off, al[im][0], al[im][1], al[im][2], al[im][3]);
            }
            const int br = lane & 7;
            const int bc = ks * 2 + ((lane >> 3) & 1);
            #pragma unroll
            for (int in = 0; in < 4; in++) {
                uint32_t off = sw_off(wn + in * 8 + br, bc);
                ldsm_x2(sBh + off, bh[in][0], bh[in][1]);
                ldsm_x2(sBl + off, bl[in][0], bl[in][1]);
            }
            #pragma unroll
            for (int im = 0; im < 4; im++)
                #pragma unroll
                for (int in = 0; in < 4; in++) {
                    mma_bf16(acc[im][in], ah[im], bh[in]);
                    mma_bf16(acc[im][in], ah[im], bl[in]);
                    mma_bf16(acc[im][in], al[im], bh[in]);
                }
        }
    }

    // epilogue
    const int rbase = m0 + wm + (lane >> 2);
    #pragma unroll
    for (int im = 0; im < 4; im++) {
        #pragma unroll
        for (int half = 0; half < 2; half++) {
            const int mg = rbase + im * 16 + half * 8;
            if (mg >= cnt) continue;
            #pragma unroll
            for (int in = 0; in < 4; in++) {
                const int col = n0 + wn + in * 8 + 2 * (lane & 3);
                float z0 = acc[im][in][2 * half]     + bias[(size_t)e * NTOT + col];
                float z1 = acc[im][in][2 * half + 1] + bias[(size_t)e * NTOT + col + 1];
                if (FIRST) {
                    float w0 = z0 / (1.f + expf(-z0));
                    float w1 = z1 / (1.f + expf(-z1));
                    unsigned short h0, l0, h1, l1;
                    split2(w0, h0, l0);
                    split2(w1, h1, l1);
                    size_t o = ((size_t)(e * T_) + mg) * H_ + col;
                    *(uint32_t*)(g_h_hi + o) = (uint32_t)h0 | ((uint32_t)h1 << 16);
                    *(uint32_t*)(g_h_lo + o) = (uint32_t)l0 | ((uint32_t)l1 << 16);
                } else {
                    size_t o = ((size_t)(e * T_) + mg) * D_ + col;
                    *(float2*)(g_partial + o) = make_float2(z0, z1);
                }
            }
        }
    }
}

// out[t] = partial[a0] + partial[a1]
__global__ void sum_kernel(float* __restrict__ out) {
    int t = blockIdx.x;
    int a0 = g_assign[2 * t], a1 = g_assign[2 * t + 1];
    const float4* p0 = (const float4*)(g_partial + (size_t)a0 * D_);
    const float4* p1 = (const float4*)(g_partial + (size_t)a1 * D_);
    float4* o = (float4*)(out + (size_t)t * D_);
    int i = threadIdx.x;
    float4 u = p0[i], w = p1[i];
    o[i] = make_float4(u.x + w.x, u.y + w.y, u.z + w.z, u.w + w.w);
}

// ---------------- launch ----------------
extern "C" void kernel_launch(void* const* d_in, const int* in_sizes, int n_in,
                              void* d_out, int out_size)
{
    const float* x      = (const float*)d_in[0];
    const float* gate_v = (const float*)d_in[1];
    const float* gate_g = (const float*)d_in[2];
    const float* gate_b = (const float*)d_in[3];
    const float* w1_v   = (const float*)d_in[4];
    const float* w1_g   = (const float*)d_in[5];
    const float* b1     = (const float*)d_in[6];
    const float* w2_v   = (const float*)d_in[7];
    const float* w2_g   = (const float*)d_in[8];
    const float* b2     = (const float*)d_in[9];
    float* out = (float*)d_out;

    cudaFuncSetAttribute(gemm_kernel<D_, true>,  cudaFuncAttributeMaxDynamicSharedMemorySize, SMEM_DYN);
    cudaFuncSetAttribute(gemm_kernel<H_, false>, cudaFuncAttributeMaxDynamicSharedMemorySize, SMEM_DYN);

    zero_counts_kernel<<<1, 32>>>();
    gate_norm_kernel<<<1, 256>>>(gate_v, gate_g);
    route_kernel<<<T_ / 8, 256>>>(x, gate_v, gate_b);
    gather_kernel<<<T_, 256>>>(x);
    wconv_kernel<<<(E_ * H_) / 8, 256>>>(w1_v, w1_g, 0, D_);
    wconv_kernel<<<(E_ * D_) / 8, 256>>>(w2_v, w2_g, 1, H_);

    gemm_kernel<D_, true><<<dim3(H_ / BN, T_ / BM, E_), NT, SMEM_DYN>>>(b1);
    gemm_kernel<H_, false><<<dim3(D_ / BN, T_ / BM, E_), NT, SMEM_DYN>>>(b2);

    sum_kernel<<<T_, 256>>>(out);
}

// round 4
// speedup vs baseline: 3.8541x; 1.5253x over previous
#include <cuda_runtime.h>
#include <cuda_fp16.h>
#include <math.h>
#include <stdint.h>

#define T_ 8192
#define D_ 1024
#define H_ 4096
#define E_ 8

#define BM 128
#define BN 128
#define BK 32
#define NT 256
#define STAGES 4
#define TILE_B (128 * 64)            // one 128x32 fp16 tile = 8192 bytes
#define STAGE_B (3 * TILE_B)         // Ahi, Alo, Bhi = 24576
#define SMEM_DYN (STAGES * STAGE_B)  // 98304

// ---------------- static device scratch ----------------
__device__ float g_gs[E_];
__device__ int   g_cnt[E_];
__device__ int   g_assign[T_ * 2];
__device__ __half g_xg_hi[(size_t)E_ * T_ * D_];
__device__ __half g_xg_lo[(size_t)E_ * T_ * D_];
__device__ __half g_w1_hi[(size_t)E_ * H_ * D_];
__device__ __half g_w2_hi[(size_t)E_ * D_ * H_];
__device__ __half g_h_hi[(size_t)E_ * T_ * H_];
__device__ __half g_h_lo[(size_t)E_ * T_ * H_];
__device__ float g_partial[(size_t)E_ * T_ * D_];

// ---------------- PTX helpers (generic sm_103-legal) ----------------
__device__ __forceinline__ uint32_t s2u(const void* p) {
    uint32_t a;
    asm("{ .reg .u64 t; cvta.to.shared.u64 t, %1; cvt.u32.u64 %0, t; }" : "=r"(a) : "l"(p));
    return a;
}
__device__ __forceinline__ void cpa16(uint32_t dst, const void* src) {
    asm volatile("cp.async.cg.shared.global [%0], [%1], 16;\n" :: "r"(dst), "l"(src) : "memory");
}
__device__ __forceinline__ void cpa_commit() { asm volatile("cp.async.commit_group;\n" ::: "memory"); }
template <int N> __device__ __forceinline__ void cpa_wait() {
    asm volatile("cp.async.wait_group %0;\n" :: "n"(N) : "memory");
}
__device__ __forceinline__ void ldsm_x4(uint32_t a, uint32_t& r0, uint32_t& r1, uint32_t& r2, uint32_t& r3) {
    asm volatile("ldmatrix.sync.aligned.m8n8.x4.shared.b16 {%0,%1,%2,%3}, [%4];"
                 : "=r"(r0), "=r"(r1), "=r"(r2), "=r"(r3) : "r"(a));
}
__device__ __forceinline__ void mma_f16(float* d, const uint32_t* a, const uint32_t* b) {
    asm volatile("mma.sync.aligned.m16n8k16.row.col.f32.f16.f16.f32 "
                 "{%0,%1,%2,%3}, {%4,%5,%6,%7}, {%8,%9}, {%0,%1,%2,%3};"
                 : "+f"(d[0]), "+f"(d[1]), "+f"(d[2]), "+f"(d[3])
                 : "r"(a[0]), "r"(a[1]), "r"(a[2]), "r"(a[3]), "r"(b[0]), "r"(b[1]));
}
__device__ __forceinline__ void split2h(float x, unsigned short& h, unsigned short& l) {
    __half hb = __float2half_rn(x);
    __half lb = __float2half_rn(x - __half2float(hb));
    h = __half_as_ushort(hb);
    l = __half_as_ushort(lb);
}
// swizzled byte offset inside a 128x32 fp16 tile (rows of 64B, 16B chunks)
__device__ __forceinline__ uint32_t sw_off(int r, int c) {
    return (uint32_t)(r * 64 + ((c ^ ((r >> 1) & 3)) << 4));
}

// ---------------- small kernels ----------------
__global__ void zero_counts_kernel() {
    if (threadIdx.x < E_) g_cnt[threadIdx.x] = 0;
}

__global__ void gate_norm_kernel(const float* __restrict__ gv, const float* __restrict__ gg) {
    int row = threadIdx.x >> 5;
    if (row >= E_) return;
    int lane = threadIdx.x & 31;
    const float4* p = (const float4*)(gv + (size_t)row * D_);
    float s = 0.f;
    for (int i = lane; i < D_ / 4; i += 32) {
        float4 a = p[i];
        s += a.x * a.x + a.y * a.y + a.z * a.z + a.w * a.w;
    }
    #pragma unroll
    for (int o = 16; o; o >>= 1) s += __shfl_xor_sync(0xffffffffu, s, o);
    if (lane == 0) g_gs[row] = gg[row] / fmaxf(sqrtf(s), 1e-12f);
}

// one warp per token: 8 gate logits, top-2, compact into expert slot lists
__global__ void route_kernel(const float* __restrict__ x,
                             const float* __restrict__ gate_v,
                             const float* __restrict__ gate_b)
{
    int t = (blockIdx.x * blockDim.x + threadIdx.x) >> 5;
    if (t >= T_) return;
    int lane = threadIdx.x & 31;
    const float4* xp = (const float4*)(x + (size_t)t * D_);
    float4 xr[8];
    #pragma unroll
    for (int i = 0; i < 8; i++) xr[i] = xp[lane + 32 * i];
    float logit[E_];
    #pragma unroll
    for (int e = 0; e < E_; e++) {
        const float4* gp = (const float4*)(gate_v + (size_t)e * D_);
        float s = 0.f;
        #pragma unroll
        for (int i = 0; i < 8; i++) {
            float4 g4 = gp[lane + 32 * i];
            s += xr[i].x * g4.x + xr[i].y * g4.y + xr[i].z * g4.z + xr[i].w * g4.w;
        }
        #pragma unroll
        for (int o = 16; o; o >>= 1) s += __shfl_xor_sync(0xffffffffu, s, o);
        logit[e] = s;
    }
    if (lane == 0) {
        int b0 = -1, b1i = -1;
        float v0 = -1e30f, v1 = -1e30f;
        #pragma unroll
        for (int e = 0; e < E_; e++) {
            float l = logit[e] * g_gs[e] + gate_b[e];
            if (l > v0)      { v1 = v0; b1i = b0; v0 = l; b0 = e; }
            else if (l > v1) { v1 = l; b1i = e; }
        }
        int e0 = min(b0, b1i), e1 = max(b0, b1i);
        int s0 = atomicAdd(&g_cnt[e0], 1);
        g_assign[2 * t] = e0 * T_ + s0;
        int s1 = atomicAdd(&g_cnt[e1], 1);
        g_assign[2 * t + 1] = e1 * T_ + s1;
    }
}

// gather x rows into assignment slots, split hi/lo fp16
__global__ void gather_kernel(const float* __restrict__ x) {
    int t = blockIdx.x;
    int i = threadIdx.x;   // 256 threads * float4 = 1024
    float4 v = ((const float4*)(x + (size_t)t * D_))[i];
    float f[4] = {v.x, v.y, v.z, v.w};
    unsigned short h[4], l[4];
    #pragma unroll
    for (int j = 0; j < 4; j++) split2h(f[j], h[j], l[j]);
    uint2 hp, lp;
    hp.x = (uint32_t)h[0] | ((uint32_t)h[1] << 16);
    hp.y = (uint32_t)h[2] | ((uint32_t)h[3] << 16);
    lp.x = (uint32_t)l[0] | ((uint32_t)l[1] << 16);
    lp.y = (uint32_t)l[2] | ((uint32_t)l[3] << 16);
    int a0 = g_assign[2 * t], a1 = g_assign[2 * t + 1];
    ((uint2*)(g_xg_hi + (size_t)a0 * D_))[i] = hp;
    ((uint2*)(g_xg_lo + (size_t)a0 * D_))[i] = lp;
    ((uint2*)(g_xg_hi + (size_t)a1 * D_))[i] = hp;
    ((uint2*)(g_xg_lo + (size_t)a1 * D_))[i] = lp;
}

// fused weight-norm + scale-fold + fp16 quantize (hi only). which=0 -> w1, 1 -> w2
__global__ void wconv_kernel(const float* __restrict__ v, const float* __restrict__ g,
                             int which, int K)
{
    int row = (blockIdx.x * blockDim.x + threadIdx.x) >> 5;
    int lane = threadIdx.x & 31;
    const float4* p = (const float4*)(v + (size_t)row * K);
    float s = 0.f;
    int n4 = K >> 2;
    for (int i = lane; i < n4; i += 32) {
        float4 a = p[i];
        s += a.x * a.x + a.y * a.y + a.z * a.z + a.w * a.w;
    }
    #pragma unroll
    for (int o = 16; o; o >>= 1) s += __shfl_xor_sync(0xffffffffu, s, o);
    float scl = g[row] / fmaxf(sqrtf(s), 1e-12f);
    __half* whi = which ? g_w2_hi : g_w1_hi;
    uint2* oh = (uint2*)(whi + (size_t)row * K);
    for (int i = lane; i < n4; i += 32) {
        float4 a = p[i];
        unsigned short h[4];
        h[0] = __half_as_ushort(__float2half_rn(a.x * scl));
        h[1] = __half_as_ushort(__float2half_rn(a.y * scl));
        h[2] = __half_as_ushort(__float2half_rn(a.z * scl));
        h[3] = __half_as_ushort(__float2half_rn(a.w * scl));
        uint2 hp;
        hp.x = (uint32_t)h[0] | ((uint32_t)h[1] << 16);
        hp.y = (uint32_t)h[2] | ((uint32_t)h[3] << 16);
        oh[i] = hp;
    }
}

// ---------------- split-fp16 HMMA GEMM: C = (Ahi + Alo) @ Bhi^T ----------------
// FIRST: [cnt,1024] @ w1^T -> swish -> g_h (hi/lo fp16)
// else : [cnt,4096] @ w2^T -> + b2  -> g_partial (fp32)
template <int K, bool FIRST>
__global__ __launch_bounds__(NT, 2) void gemm_kernel(const float* __restrict__ bias)
{
    const int e   = blockIdx.z;
    const int cnt = g_cnt[e];
    const int m0  = blockIdx.y * BM;
    if (m0 >= cnt) return;
    const int n0  = blockIdx.x * BN;
    constexpr int NTOT = FIRST ? H_ : D_;
    constexpr int NC = K / BK;

    extern __shared__ char smem_raw[];
    const uint32_t sbase = s2u(smem_raw);
    const int tid  = threadIdx.x;
    const int lane = tid & 31;
    const int wid  = tid >> 5;
    const int wm   = (wid & 1) * 64;   // warp m offset in tile
    const int wn   = (wid >> 1) * 32;  // warp n offset in tile

    const size_t arow = (size_t)(e * T_ + m0);
    const __half* Ahi_g = (FIRST ? g_xg_hi : g_h_hi) + arow * K;
    const __half* Alo_g = (FIRST ? g_xg_lo : g_h_lo) + arow * K;
    const __half* Bhi_g = (FIRST ? g_w1_hi : g_w2_hi) + ((size_t)e * NTOT + n0) * K;

    auto load_chunk = [&](int c, int s) {
        uint32_t stg = sbase + s * STAGE_B;
        #pragma unroll
        for (int q = 0; q < 6; q++) {
            int i   = tid + q * NT;       // 0..1535
            int mtx = i >> 9;             // 0 Ahi 1 Alo 2 Bhi
            int r   = (i >> 2) & 127;
            int cc  = i & 3;
            const __half* src = (mtx == 0) ? Ahi_g : (mtx == 1) ? Alo_g : Bhi_g;
            src += (size_t)r * K + c * BK + cc * 8;
            cpa16(stg + mtx * TILE_B + sw_off(r, cc), src);
        }
    };

    float acc[4][4][4] = {};

    // prologue: stage first 3 chunks
    #pragma unroll
    for (int c = 0; c < STAGES - 1; ++c) { load_chunk(c, c); cpa_commit(); }

    for (int c = 0; c < NC; ++c) {
        const int s = c & (STAGES - 1);
        cpa_wait<STAGES - 2>();
        __syncthreads();
        const int cn = c + STAGES - 1;
        if (cn < NC) load_chunk(cn, cn & (STAGES - 1));
        cpa_commit();

        const uint32_t sAh = sbase + s * STAGE_B;
        const uint32_t sAl = sAh + TILE_B;
        const uint32_t sBh = sAh + 2 * TILE_B;

        #pragma unroll
        for (int ks = 0; ks < 2; ++ks) {
            uint32_t ah[4][4], al[4][4], bh[4][2];
            const int ar = lane & 15;
            const int ac = ks * 2 + (lane >> 4);
            #pragma unroll
            for (int im = 0; im < 4; im++) {
                uint32_t off = sw_off(wm + im * 16 + ar, ac);
                ldsm_x4(sAh + off, ah[im][0], ah[im][1], ah[im][2], ah[im][3]);
                ldsm_x4(sAl + off, al[im][0], al[im][1], al[im][2], al[im][3]);
            }
            // B: one ldmatrix.x4 covers 2 n-frags (16 rows) for this k16
            const int br = (lane & 7) + ((lane >> 4) << 3);
            const int bc = ks * 2 + ((lane >> 3) & 1);
            #pragma unroll
            for (int half = 0; half < 2; half++) {
                uint32_t off = sw_off(wn + half * 16 + br, bc);
                ldsm_x4(sBh + off, bh[2 * half][0], bh[2 * half][1],
                                   bh[2 * half + 1][0], bh[2 * half + 1][1]);
            }
            #pragma unroll
            for (int im = 0; im < 4; im++)
                #pragma unroll
                for (int in = 0; in < 4; in++) {
                    mma_f16(acc[im][in], ah[im], bh[in]);
                    mma_f16(acc[im][in], al[im], bh[in]);
                }
        }
    }

    // epilogue
    const int rbase = m0 + wm + (lane >> 2);
    #pragma unroll
    for (int im = 0; im < 4; im++) {
        #pragma unroll
        for (int half = 0; half < 2; half++) {
            const int mg = rbase + im * 16 + half * 8;
            if (mg >= cnt) continue;
            #pragma unroll
            for (int in = 0; in < 4; in++) {
                const int col = n0 + wn + in * 8 + 2 * (lane & 3);
                float z0 = acc[im][in][2 * half]     + bias[(size_t)e * NTOT + col];
                float z1 = acc[im][in][2 * half + 1] + bias[(size_t)e * NTOT + col + 1];
                if (FIRST) {
                    float w0 = z0 * __frcp_rn(1.f + __expf(-z0));
                    float w1 = z1 * __frcp_rn(1.f + __expf(-z1));
                    unsigned short h0, l0, h1, l1;
                    split2h(w0, h0, l0);
                    split2h(w1, h1, l1);
                    size_t o = ((size_t)(e * T_) + mg) * H_ + col;
                    *(uint32_t*)(g_h_hi + o) = (uint32_t)h0 | ((uint32_t)h1 << 16);
                    *(uint32_t*)(g_h_lo + o) = (uint32_t)l0 | ((uint32_t)l1 << 16);
                } else {
                    size_t o = ((size_t)(e * T_) + mg) * D_ + col;
                    *(float2*)(g_partial + o) = make_float2(z0, z1);
                }
            }
        }
    }
}

// out[t] = partial[a0] + partial[a1]
__global__ void sum_kernel(float* __restrict__ out) {
    int t = blockIdx.x;
    int a0 = g_assign[2 * t], a1 = g_assign[2 * t + 1];
    const float4* p0 = (const float4*)(g_partial + (size_t)a0 * D_);
    const float4* p1 = (const float4*)(g_partial + (size_t)a1 * D_);
    float4* o = (float4*)(out + (size_t)t * D_);
    int i = threadIdx.x;
    float4 u = p0[i], w = p1[i];
    o[i] = make_float4(u.x + w.x, u.y + w.y, u.z + w.z, u.w + w.w);
}

// ---------------- launch ----------------
extern "C" void kernel_launch(void* const* d_in, const int* in_sizes, int n_in,
                              void* d_out, int out_size)
{
    const float* x      = (const float*)d_in[0];
    const float* gate_v = (const float*)d_in[1];
    const float* gate_g = (const float*)d_in[2];
    const float* gate_b = (const float*)d_in[3];
    const float* w1_v   = (const float*)d_in[4];
    const float* w1_g   = (const float*)d_in[5];
    const float* b1     = (const float*)d_in[6];
    const float* w2_v   = (const float*)d_in[7];
    const float* w2_g   = (const float*)d_in[8];
    const float* b2     = (const float*)d_in[9];
    float* out = (float*)d_out;

    cudaFuncSetAttribute(gemm_kernel<D_, true>,  cudaFuncAttributeMaxDynamicSharedMemorySize, SMEM_DYN);
    cudaFuncSetAttribute(gemm_kernel<H_, false>, cudaFuncAttributeMaxDynamicSharedMemorySize, SMEM_DYN);

    zero_counts_kernel<<<1, 32>>>();
    gate_norm_kernel<<<1, 256>>>(gate_v, gate_g);
    route_kernel<<<T_ / 8, 256>>>(x, gate_v, gate_b);
    gather_kernel<<<T_, 256>>>(x);
    wconv_kernel<<<(E_ * H_) / 8, 256>>>(w1_v, w1_g, 0, D_);
    wconv_kernel<<<(E_ * D_) / 8, 256>>>(w2_v, w2_g, 1, H_);

    gemm_kernel<D_, true><<<dim3(H_ / BN, T_ / BM, E_), NT, SMEM_DYN>>>(b1);
    gemm_kernel<H_, false><<<dim3(D_ / BN, T_ / BM, E_), NT, SMEM_DYN>>>(b2);

    sum_kernel<<<T_, 256>>>(out);
}

// round 5
// speedup vs baseline: 6.5724x; 1.7053x over previous
#include <cuda_runtime.h>
#include <cuda_fp16.h>
#include <math.h>
#include <stdint.h>

#define T_ 8192
#define D_ 1024
#define H_ 4096
#define E_ 8

#define BM 128
#define BN 128
#define BK 32
#define NT 256
#define STAGES 4
#define TILE_B (128 * 64)            // one 128x32 fp16 tile = 8192 bytes
#define STAGE_B (2 * TILE_B)         // A, B = 16384
#define SMEM_DYN (STAGES * STAGE_B)  // 65536

// ---------------- static device scratch ----------------
__device__ float g_gs[E_];
__device__ int   g_cnt[E_];
__device__ int   g_assign[T_ * 2];
__device__ __half g_xg[(size_t)E_ * T_ * D_];
__device__ __half g_w1[(size_t)E_ * H_ * D_];
__device__ __half g_w2[(size_t)E_ * D_ * H_];
__device__ __half g_h[(size_t)E_ * T_ * H_];
__device__ float g_partial[(size_t)E_ * T_ * D_];

// ---------------- PTX helpers (generic sm_103-legal) ----------------
__device__ __forceinline__ uint32_t s2u(const void* p) {
    uint32_t a;
    asm("{ .reg .u64 t; cvta.to.shared.u64 t, %1; cvt.u32.u64 %0, t; }" : "=r"(a) : "l"(p));
    return a;
}
__device__ __forceinline__ void cpa16(uint32_t dst, const void* src) {
    asm volatile("cp.async.cg.shared.global [%0], [%1], 16;\n" :: "r"(dst), "l"(src) : "memory");
}
__device__ __forceinline__ void cpa_commit() { asm volatile("cp.async.commit_group;\n" ::: "memory"); }
template <int N> __device__ __forceinline__ void cpa_wait() {
    asm volatile("cp.async.wait_group %0;\n" :: "n"(N) : "memory");
}
__device__ __forceinline__ void ldsm_x4(uint32_t a, uint32_t& r0, uint32_t& r1, uint32_t& r2, uint32_t& r3) {
    asm volatile("ldmatrix.sync.aligned.m8n8.x4.shared.b16 {%0,%1,%2,%3}, [%4];"
                 : "=r"(r0), "=r"(r1), "=r"(r2), "=r"(r3) : "r"(a));
}
__device__ __forceinline__ void mma_f16(float* d, const uint32_t* a, const uint32_t* b) {
    asm volatile("mma.sync.aligned.m16n8k16.row.col.f32.f16.f16.f32 "
                 "{%0,%1,%2,%3}, {%4,%5,%6,%7}, {%8,%9}, {%0,%1,%2,%3};"
                 : "+f"(d[0]), "+f"(d[1]), "+f"(d[2]), "+f"(d[3])
                 : "r"(a[0]), "r"(a[1]), "r"(a[2]), "r"(a[3]), "r"(b[0]), "r"(b[1]));
}
// swizzled byte offset inside a 128x32 fp16 tile (rows of 64B, 16B chunks)
__device__ __forceinline__ uint32_t sw_off(int r, int c) {
    return (uint32_t)(r * 64 + ((c ^ ((r >> 1) & 3)) << 4));
}

// ---------------- small kernels ----------------
__global__ void zero_counts_kernel() {
    if (threadIdx.x < E_) g_cnt[threadIdx.x] = 0;
}

__global__ void gate_norm_kernel(const float* __restrict__ gv, const float* __restrict__ gg) {
    int row = threadIdx.x >> 5;
    if (row >= E_) return;
    int lane = threadIdx.x & 31;
    const float4* p = (const float4*)(gv + (size_t)row * D_);
    float s = 0.f;
    for (int i = lane; i < D_ / 4; i += 32) {
        float4 a = p[i];
        s += a.x * a.x + a.y * a.y + a.z * a.z + a.w * a.w;
    }
    #pragma unroll
    for (int o = 16; o; o >>= 1) s += __shfl_xor_sync(0xffffffffu, s, o);
    if (lane == 0) g_gs[row] = gg[row] / fmaxf(sqrtf(s), 1e-12f);
}

// one warp per token: 8 gate logits, top-2, compact into expert slot lists
__global__ void route_kernel(const float* __restrict__ x,
                             const float* __restrict__ gate_v,
                             const float* __restrict__ gate_b)
{
    int t = (blockIdx.x * blockDim.x + threadIdx.x) >> 5;
    if (t >= T_) return;
    int lane = threadIdx.x & 31;
    const float4* xp = (const float4*)(x + (size_t)t * D_);
    float4 xr[8];
    #pragma unroll
    for (int i = 0; i < 8; i++) xr[i] = xp[lane + 32 * i];
    float logit[E_];
    #pragma unroll
    for (int e = 0; e < E_; e++) {
        const float4* gp = (const float4*)(gate_v + (size_t)e * D_);
        float s = 0.f;
        #pragma unroll
        for (int i = 0; i < 8; i++) {
            float4 g4 = gp[lane + 32 * i];
            s += xr[i].x * g4.x + xr[i].y * g4.y + xr[i].z * g4.z + xr[i].w * g4.w;
        }
        #pragma unroll
        for (int o = 16; o; o >>= 1) s += __shfl_xor_sync(0xffffffffu, s, o);
        logit[e] = s;
    }
    if (lane == 0) {
        int b0 = -1, b1i = -1;
        float v0 = -1e30f, v1 = -1e30f;
        #pragma unroll
        for (int e = 0; e < E_; e++) {
            float l = logit[e] * g_gs[e] + gate_b[e];
            if (l > v0)      { v1 = v0; b1i = b0; v0 = l; b0 = e; }
            else if (l > v1) { v1 = l; b1i = e; }
        }
        int e0 = min(b0, b1i), e1 = max(b0, b1i);
        int s0 = atomicAdd(&g_cnt[e0], 1);
        g_assign[2 * t] = e0 * T_ + s0;
        int s1 = atomicAdd(&g_cnt[e1], 1);
        g_assign[2 * t + 1] = e1 * T_ + s1;
    }
}

// gather x rows into assignment slots as fp16
__global__ void gather_kernel(const float* __restrict__ x) {
    int t = blockIdx.x;
    int i = threadIdx.x;   // 256 threads * float4 = 1024
    float4 v = ((const float4*)(x + (size_t)t * D_))[i];
    unsigned short h[4];
    h[0] = __half_as_ushort(__float2half_rn(v.x));
    h[1] = __half_as_ushort(__float2half_rn(v.y));
    h[2] = __half_as_ushort(__float2half_rn(v.z));
    h[3] = __half_as_ushort(__float2half_rn(v.w));
    uint2 hp;
    hp.x = (uint32_t)h[0] | ((uint32_t)h[1] << 16);
    hp.y = (uint32_t)h[2] | ((uint32_t)h[3] << 16);
    int a0 = g_assign[2 * t], a1 = g_assign[2 * t + 1];
    ((uint2*)(g_xg + (size_t)a0 * D_))[i] = hp;
    ((uint2*)(g_xg + (size_t)a1 * D_))[i] = hp;
}

// fused weight-norm + scale-fold + fp16 quantize. which=0 -> w1, 1 -> w2
__global__ void wconv_kernel(const float* __restrict__ v, const float* __restrict__ g,
                             int which, int K)
{
    int row = (blockIdx.x * blockDim.x + threadIdx.x) >> 5;
    int lane = threadIdx.x & 31;
    const float4* p = (const float4*)(v + (size_t)row * K);
    float s = 0.f;
    int n4 = K >> 2;
    for (int i = lane; i < n4; i += 32) {
        float4 a = p[i];
        s += a.x * a.x + a.y * a.y + a.z * a.z + a.w * a.w;
    }
    #pragma unroll
    for (int o = 16; o; o >>= 1) s += __shfl_xor_sync(0xffffffffu, s, o);
    float scl = g[row] / fmaxf(sqrtf(s), 1e-12f);
    __half* whi = which ? g_w2 : g_w1;
    uint2* oh = (uint2*)(whi + (size_t)row * K);
    for (int i = lane; i < n4; i += 32) {
        float4 a = p[i];
        unsigned short h[4];
        h[0] = __half_as_ushort(__float2half_rn(a.x * scl));
        h[1] = __half_as_ushort(__float2half_rn(a.y * scl));
        h[2] = __half_as_ushort(__float2half_rn(a.z * scl));
        h[3] = __half_as_ushort(__float2half_rn(a.w * scl));
        uint2 hp;
        hp.x = (uint32_t)h[0] | ((uint32_t)h[1] << 16);
        hp.y = (uint32_t)h[2] | ((uint32_t)h[3] << 16);
        oh[i] = hp;
    }
}

// ---------------- fp16 HMMA GEMM (mma.sync m16n8k16) ----------------
// FIRST: [cnt,1024] @ w1^T -> swish -> g_h (fp16)
// else : [cnt,4096] @ w2^T -> + b2  -> g_partial (fp32)
template <int K, bool FIRST>
__global__ __launch_bounds__(NT, 2) void gemm_kernel(const float* __restrict__ bias)
{
    const int e   = blockIdx.z;
    const int cnt = g_cnt[e];
    const int m0  = blockIdx.y * BM;
    if (m0 >= cnt) return;
    const int n0  = blockIdx.x * BN;
    constexpr int NTOT = FIRST ? H_ : D_;
    constexpr int NC = K / BK;

    extern __shared__ char smem_raw[];
    const uint32_t sbase = s2u(smem_raw);
    const int tid  = threadIdx.x;
    const int lane = tid & 31;
    const int wid  = tid >> 5;
    const int wm   = (wid & 1) * 64;   // warp m offset in tile
    const int wn   = (wid >> 1) * 32;  // warp n offset in tile

    const size_t arow = (size_t)(e * T_ + m0);
    const __half* A_g = (FIRST ? g_xg : g_h) + arow * K;
    const __half* B_g = (FIRST ? g_w1 : g_w2) + ((size_t)e * NTOT + n0) * K;

    auto load_chunk = [&](int c, int s) {
        uint32_t stg = sbase + s * STAGE_B;
        #pragma unroll
        for (int q = 0; q < 4; q++) {
            int i   = tid + q * NT;       // 0..1023
            int mtx = i >> 9;             // 0 A, 1 B
            int r   = (i >> 2) & 127;
            int cc  = i & 3;
            const __half* src = (mtx == 0) ? A_g : B_g;
            src += (size_t)r * K + c * BK + cc * 8;
            cpa16(stg + mtx * TILE_B + sw_off(r, cc), src);
        }
    };

    float acc[4][4][4] = {};

    // prologue: stage first 3 chunks
    #pragma unroll
    for (int c = 0; c < STAGES - 1; ++c) { load_chunk(c, c); cpa_commit(); }

    for (int c = 0; c < NC; ++c) {
        const int s = c & (STAGES - 1);
        cpa_wait<STAGES - 2>();
        __syncthreads();
        const int cn = c + STAGES - 1;
        if (cn < NC) load_chunk(cn, cn & (STAGES - 1));
        cpa_commit();

        const uint32_t sA = sbase + s * STAGE_B;
        const uint32_t sB = sA + TILE_B;

        #pragma unroll
        for (int ks = 0; ks < 2; ++ks) {
            uint32_t ah[4][4], bh[4][2];
            const int ar = lane & 15;
            const int ac = ks * 2 + (lane >> 4);
            #pragma unroll
            for (int im = 0; im < 4; im++) {
                uint32_t off = sw_off(wm + im * 16 + ar, ac);
                ldsm_x4(sA + off, ah[im][0], ah[im][1], ah[im][2], ah[im][3]);
            }
            // B: one ldmatrix.x4 covers 2 n-frags (16 rows) for this k16
            const int br = (lane & 7) + ((lane >> 4) << 3);
            const int bc = ks * 2 + ((lane >> 3) & 1);
            #pragma unroll
            for (int half = 0; half < 2; half++) {
                uint32_t off = sw_off(wn + half * 16 + br, bc);
                ldsm_x4(sB + off, bh[2 * half][0], bh[2 * half][1],
                                  bh[2 * half + 1][0], bh[2 * half + 1][1]);
            }
            #pragma unroll
            for (int im = 0; im < 4; im++)
                #pragma unroll
                for (int in = 0; in < 4; in++)
                    mma_f16(acc[im][in], ah[im], bh[in]);
        }
    }

    // epilogue
    const int rbase = m0 + wm + (lane >> 2);
    #pragma unroll
    for (int im = 0; im < 4; im++) {
        #pragma unroll
        for (int half = 0; half < 2; half++) {
            const int mg = rbase + im * 16 + half * 8;
            if (mg >= cnt) continue;
            #pragma unroll
            for (int in = 0; in < 4; in++) {
                const int col = n0 + wn + in * 8 + 2 * (lane & 3);
                float z0 = acc[im][in][2 * half]     + bias[(size_t)e * NTOT + col];
                float z1 = acc[im][in][2 * half + 1] + bias[(size_t)e * NTOT + col + 1];
                if (FIRST) {
                    float w0 = z0 * __frcp_rn(1.f + __expf(-z0));
                    float w1 = z1 * __frcp_rn(1.f + __expf(-z1));
                    unsigned short h0 = __half_as_ushort(__float2half_rn(w0));
                    unsigned short h1 = __half_as_ushort(__float2half_rn(w1));
                    size_t o = ((size_t)(e * T_) + mg) * H_ + col;
                    *(uint32_t*)(g_h + o) = (uint32_t)h0 | ((uint32_t)h1 << 16);
                } else {
                    size_t o = ((size_t)(e * T_) + mg) * D_ + col;
                    *(float2*)(g_partial + o) = make_float2(z0, z1);
                }
            }
        }
    }
}

// out[t] = partial[a0] + partial[a1]
__global__ void sum_kernel(float* __restrict__ out) {
    int t = blockIdx.x;
    int a0 = g_assign[2 * t], a1 = g_assign[2 * t + 1];
    const float4* p0 = (const float4*)(g_partial + (size_t)a0 * D_);
    const float4* p1 = (const float4*)(g_partial + (size_t)a1 * D_);
    float4* o = (float4*)(out + (size_t)t * D_);
    int i = threadIdx.x;
    float4 u = p0[i], w = p1[i];
    o[i] = make_float4(u.x + w.x, u.y + w.y, u.z + w.z, u.w + w.w);
}

// ---------------- launch ----------------
extern "C" void kernel_launch(void* const* d_in, const int* in_sizes, int n_in,
                              void* d_out, int out_size)
{
    const float* x      = (const float*)d_in[0];
    const float* gate_v = (const float*)d_in[1];
    const float* gate_g = (const float*)d_in[2];
    const float* gate_b = (const float*)d_in[3];
    const float* w1_v   = (const float*)d_in[4];
    const float* w1_g   = (const float*)d_in[5];
    const float* b1     = (const float*)d_in[6];
    const float* w2_v   = (const float*)d_in[7];
    const float* w2_g   = (const float*)d_in[8];
    const float* b2     = (const float*)d_in[9];
    float* out = (float*)d_out;

    cudaFuncSetAttribute(gemm_kernel<D_, true>,  cudaFuncAttributeMaxDynamicSharedMemorySize, SMEM_DYN);
    cudaFuncSetAttribute(gemm_kernel<H_, false>, cudaFuncAttributeMaxDynamicSharedMemorySize, SMEM_DYN);

    zero_counts_kernel<<<1, 32>>>();
    gate_norm_kernel<<<1, 256>>>(gate_v, gate_g);
    route_kernel<<<T_ / 8, 256>>>(x, gate_v, gate_b);
    gather_kernel<<<T_, 256>>>(x);
    wconv_kernel<<<(E_ * H_) / 8, 256>>>(w1_v, w1_g, 0, D_);
    wconv_kernel<<<(E_ * D_) / 8, 256>>>(w2_v, w2_g, 1, H_);

    gemm_kernel<D_, true><<<dim3(H_ / BN, T_ / BM, E_), NT, SMEM_DYN>>>(b1);
    gemm_kernel<H_, false><<<dim3(D_ / BN, T_ / BM, E_), NT, SMEM_DYN>>>(b2);

    sum_kernel<<<T_, 256>>>(out);
}

// round 6
// speedup vs baseline: 7.8067x; 1.1878x over previous
#include <cuda_runtime.h>
#include <cuda_fp16.h>
#include <math.h>
#include <stdint.h>

#define T_ 8192
#define D_ 1024
#define H_ 4096
#define E_ 8

#define BM 128
#define BN 128
#define BK 64
#define NT 256
#define STAGES 3
#define TILE_B (128 * 128)           // one 128x64 fp16 tile = 16384 bytes
#define STAGE_B (2 * TILE_B)         // A, B = 32768
#define SMEM_DYN (STAGES * STAGE_B)  // 98304

// ---------------- static device scratch ----------------
__device__ float g_gs[E_];
__device__ int   g_cnt[E_];
__device__ int   g_assign[T_ * 2];
__device__ __half g_xg[(size_t)E_ * T_ * D_];
__device__ __half g_w1[(size_t)E_ * H_ * D_];
__device__ __half g_w2[(size_t)E_ * D_ * H_];
__device__ __half g_h[(size_t)E_ * T_ * H_];
__device__ float g_partial[(size_t)E_ * T_ * D_];

// ---------------- PTX helpers (generic sm_103-legal) ----------------
__device__ __forceinline__ uint32_t s2u(const void* p) {
    uint32_t a;
    asm("{ .reg .u64 t; cvta.to.shared.u64 t, %1; cvt.u32.u64 %0, t; }" : "=r"(a) : "l"(p));
    return a;
}
__device__ __forceinline__ void cpa16(uint32_t dst, const void* src) {
    asm volatile("cp.async.cg.shared.global [%0], [%1], 16;\n" :: "r"(dst), "l"(src) : "memory");
}
__device__ __forceinline__ void cpa_commit() { asm volatile("cp.async.commit_group;\n" ::: "memory"); }
template <int N> __device__ __forceinline__ void cpa_wait() {
    asm volatile("cp.async.wait_group %0;\n" :: "n"(N) : "memory");
}
__device__ __forceinline__ void ldsm_x4(uint32_t a, uint32_t& r0, uint32_t& r1, uint32_t& r2, uint32_t& r3) {
    asm volatile("ldmatrix.sync.aligned.m8n8.x4.shared.b16 {%0,%1,%2,%3}, [%4];"
                 : "=r"(r0), "=r"(r1), "=r"(r2), "=r"(r3) : "r"(a));
}
__device__ __forceinline__ void mma_f16(float* d, const uint32_t* a, const uint32_t* b) {
    asm volatile("mma.sync.aligned.m16n8k16.row.col.f32.f16.f16.f32 "
                 "{%0,%1,%2,%3}, {%4,%5,%6,%7}, {%8,%9}, {%0,%1,%2,%3};"
                 : "+f"(d[0]), "+f"(d[1]), "+f"(d[2]), "+f"(d[3])
                 : "r"(a[0]), "r"(a[1]), "r"(a[2]), "r"(a[3]), "r"(b[0]), "r"(b[1]));
}
// swizzled byte offset inside a 128x64 fp16 tile (rows of 128B, 16B chunks)
__device__ __forceinline__ uint32_t sw_off(int r, int c) {
    return (uint32_t)(r * 128 + ((c ^ (r & 7)) << 4));
}

// ---------------- small kernels ----------------
__global__ void zero_counts_kernel() {
    if (threadIdx.x < E_) g_cnt[threadIdx.x] = 0;
}

__global__ void gate_norm_kernel(const float* __restrict__ gv, const float* __restrict__ gg) {
    int row = threadIdx.x >> 5;
    if (row >= E_) return;
    int lane = threadIdx.x & 31;
    const float4* p = (const float4*)(gv + (size_t)row * D_);
    float s = 0.f;
    for (int i = lane; i < D_ / 4; i += 32) {
        float4 a = p[i];
        s += a.x * a.x + a.y * a.y + a.z * a.z + a.w * a.w;
    }
    #pragma unroll
    for (int o = 16; o; o >>= 1) s += __shfl_xor_sync(0xffffffffu, s, o);
    if (lane == 0) g_gs[row] = gg[row] / fmaxf(sqrtf(s), 1e-12f);
}

// one warp per token: 8 gate logits, top-2, compact into expert slot lists
__global__ void route_kernel(const float* __restrict__ x,
                             const float* __restrict__ gate_v,
                             const float* __restrict__ gate_b)
{
    int t = (blockIdx.x * blockDim.x + threadIdx.x) >> 5;
    if (t >= T_) return;
    int lane = threadIdx.x & 31;
    const float4* xp = (const float4*)(x + (size_t)t * D_);
    float4 xr[8];
    #pragma unroll
    for (int i = 0; i < 8; i++) xr[i] = xp[lane + 32 * i];
    float logit[E_];
    #pragma unroll
    for (int e = 0; e < E_; e++) {
        const float4* gp = (const float4*)(gate_v + (size_t)e * D_);
        float s = 0.f;
        #pragma unroll
        for (int i = 0; i < 8; i++) {
            float4 g4 = gp[lane + 32 * i];
            s += xr[i].x * g4.x + xr[i].y * g4.y + xr[i].z * g4.z + xr[i].w * g4.w;
        }
        #pragma unroll
        for (int o = 16; o; o >>= 1) s += __shfl_xor_sync(0xffffffffu, s, o);
        logit[e] = s;
    }
    if (lane == 0) {
        int b0 = -1, b1i = -1;
        float v0 = -1e30f, v1 = -1e30f;
        #pragma unroll
        for (int e = 0; e < E_; e++) {
            float l = logit[e] * g_gs[e] + gate_b[e];
            if (l > v0)      { v1 = v0; b1i = b0; v0 = l; b0 = e; }
            else if (l > v1) { v1 = l; b1i = e; }
        }
        int e0 = min(b0, b1i), e1 = max(b0, b1i);
        int s0 = atomicAdd(&g_cnt[e0], 1);
        g_assign[2 * t] = e0 * T_ + s0;
        int s1 = atomicAdd(&g_cnt[e1], 1);
        g_assign[2 * t + 1] = e1 * T_ + s1;
    }
}

// gather x rows into assignment slots as fp16
__global__ void gather_kernel(const float* __restrict__ x) {
    int t = blockIdx.x;
    int i = threadIdx.x;   // 256 threads * float4 = 1024
    float4 v = ((const float4*)(x + (size_t)t * D_))[i];
    unsigned short h[4];
    h[0] = __half_as_ushort(__float2half_rn(v.x));
    h[1] = __half_as_ushort(__float2half_rn(v.y));
    h[2] = __half_as_ushort(__float2half_rn(v.z));
    h[3] = __half_as_ushort(__float2half_rn(v.w));
    uint2 hp;
    hp.x = (uint32_t)h[0] | ((uint32_t)h[1] << 16);
    hp.y = (uint32_t)h[2] | ((uint32_t)h[3] << 16);
    int a0 = g_assign[2 * t], a1 = g_assign[2 * t + 1];
    ((uint2*)(g_xg + (size_t)a0 * D_))[i] = hp;
    ((uint2*)(g_xg + (size_t)a1 * D_))[i] = hp;
}

// fused weight-norm + scale-fold + fp16 quantize. which=0 -> w1, 1 -> w2
__global__ void wconv_kernel(const float* __restrict__ v, const float* __restrict__ g,
                             int which, int K)
{
    int row = (blockIdx.x * blockDim.x + threadIdx.x) >> 5;
    int lane = threadIdx.x & 31;
    const float4* p = (const float4*)(v + (size_t)row * K);
    float s = 0.f;
    int n4 = K >> 2;
    for (int i = lane; i < n4; i += 32) {
        float4 a = p[i];
        s += a.x * a.x + a.y * a.y + a.z * a.z + a.w * a.w;
    }
    #pragma unroll
    for (int o = 16; o; o >>= 1) s += __shfl_xor_sync(0xffffffffu, s, o);
    float scl = g[row] / fmaxf(sqrtf(s), 1e-12f);
    __half* whi = which ? g_w2 : g_w1;
    uint2* oh = (uint2*)(whi + (size_t)row * K);
    for (int i = lane; i < n4; i += 32) {
        float4 a = p[i];
        unsigned short h[4];
        h[0] = __half_as_ushort(__float2half_rn(a.x * scl));
        h[1] = __half_as_ushort(__float2half_rn(a.y * scl));
        h[2] = __half_as_ushort(__float2half_rn(a.z * scl));
        h[3] = __half_as_ushort(__float2half_rn(a.w * scl));
        uint2 hp;
        hp.x = (uint32_t)h[0] | ((uint32_t)h[1] << 16);
        hp.y = (uint32_t)h[2] | ((uint32_t)h[3] << 16);
        oh[i] = hp;
    }
}

// ---------------- fp16 HMMA GEMM (mma.sync m16n8k16, BK=64) ----------------
// FIRST: [cnt,1024] @ w1^T -> swish -> g_h (fp16)
// else : [cnt,4096] @ w2^T -> + b2  -> g_partial (fp32)
template <int K, bool FIRST>
__global__ __launch_bounds__(NT, 2) void gemm_kernel(const float* __restrict__ bias)
{
    const int e   = blockIdx.z;
    const int cnt = g_cnt[e];
    const int m0  = blockIdx.y * BM;
    if (m0 >= cnt) return;
    const int n0  = blockIdx.x * BN;
    constexpr int NTOT = FIRST ? H_ : D_;
    constexpr int NC = K / BK;

    extern __shared__ char smem_raw[];
    const uint32_t sbase = s2u(smem_raw);
    const int tid  = threadIdx.x;
    const int lane = tid & 31;
    const int wid  = tid >> 5;
    const int wm   = (wid & 1) * 64;   // warp m offset in tile
    const int wn   = (wid >> 1) * 32;  // warp n offset in tile

    const size_t arow = (size_t)(e * T_ + m0);
    const __half* A_g = (FIRST ? g_xg : g_h) + arow * K;
    const __half* B_g = (FIRST ? g_w1 : g_w2) + ((size_t)e * NTOT + n0) * K;

    auto load_chunk = [&](int c, int s) {
        uint32_t stg = sbase + s * STAGE_B;
        #pragma unroll
        for (int q = 0; q < 8; q++) {
            int i   = tid + q * NT;       // 0..2047
            int mtx = i >> 10;            // 0 A, 1 B
            int rem = i & 1023;
            int r   = rem >> 3;
            int cc  = rem & 7;
            const __half* src = (mtx == 0) ? A_g : B_g;
            src += (size_t)r * K + c * BK + cc * 8;
            cpa16(stg + mtx * TILE_B + sw_off(r, cc), src);
        }
    };

    float acc[4][4][4] = {};

    // prologue: stage first STAGES-1 chunks
    #pragma unroll
    for (int c = 0; c < STAGES - 1; ++c) { load_chunk(c, c); cpa_commit(); }

    int s = 0;
    for (int c = 0; c < NC; ++c) {
        cpa_wait<STAGES - 2>();
        __syncthreads();
        const int cn = c + STAGES - 1;
        if (cn < NC) {
            int sn = s + STAGES - 1;
            if (sn >= STAGES) sn -= STAGES;
            load_chunk(cn, sn);
        }
        cpa_commit();

        const uint32_t sA = sbase + s * STAGE_B;
        const uint32_t sB = sA + TILE_B;

        #pragma unroll
        for (int ks = 0; ks < 4; ++ks) {
            uint32_t ah[4][4], bh[4][2];
            const int ar = lane & 15;
            const int ac = ks * 2 + (lane >> 4);
            #pragma unroll
            for (int im = 0; im < 4; im++) {
                uint32_t off = sw_off(wm + im * 16 + ar, ac);
                ldsm_x4(sA + off, ah[im][0], ah[im][1], ah[im][2], ah[im][3]);
            }
            // B: one ldmatrix.x4 covers 2 n-frags (16 rows) for this k16
            const int br = (lane & 7) + ((lane >> 4) << 3);
            const int bc = ks * 2 + ((lane >> 3) & 1);
            #pragma unroll
            for (int half = 0; half < 2; half++) {
                uint32_t off = sw_off(wn + half * 16 + br, bc);
                ldsm_x4(sB + off, bh[2 * half][0], bh[2 * half][1],
                                  bh[2 * half + 1][0], bh[2 * half + 1][1]);
            }
            #pragma unroll
            for (int im = 0; im < 4; im++)
                #pragma unroll
                for (int in = 0; in < 4; in++)
                    mma_f16(acc[im][in], ah[im], bh[in]);
        }
        if (++s == STAGES) s = 0;
    }

    // epilogue
    const int rbase = m0 + wm + (lane >> 2);
    #pragma unroll
    for (int im = 0; im < 4; im++) {
        #pragma unroll
        for (int half = 0; half < 2; half++) {
            const int mg = rbase + im * 16 + half * 8;
            if (mg >= cnt) continue;
            #pragma unroll
            for (int in = 0; in < 4; in++) {
                const int col = n0 + wn + in * 8 + 2 * (lane & 3);
                float z0 = acc[im][in][2 * half]     + bias[(size_t)e * NTOT + col];
                float z1 = acc[im][in][2 * half + 1] + bias[(size_t)e * NTOT + col + 1];
                if (FIRST) {
                    float w0 = z0 * __frcp_rn(1.f + __expf(-z0));
                    float w1 = z1 * __frcp_rn(1.f + __expf(-z1));
                    unsigned short h0 = __half_as_ushort(__float2half_rn(w0));
                    unsigned short h1 = __half_as_ushort(__float2half_rn(w1));
                    size_t o = ((size_t)(e * T_) + mg) * H_ + col;
                    *(uint32_t*)(g_h + o) = (uint32_t)h0 | ((uint32_t)h1 << 16);
                } else {
                    size_t o = ((size_t)(e * T_) + mg) * D_ + col;
                    *(float2*)(g_partial + o) = make_float2(z0, z1);
                }
            }
        }
    }
}

// out[t] = partial[a0] + partial[a1]
__global__ void sum_kernel(float* __restrict__ out) {
    int t = blockIdx.x;
    int a0 = g_assign[2 * t], a1 = g_assign[2 * t + 1];
    const float4* p0 = (const float4*)(g_partial + (size_t)a0 * D_);
    const float4* p1 = (const float4*)(g_partial + (size_t)a1 * D_);
    float4* o = (float4*)(out + (size_t)t * D_);
    int i = threadIdx.x;
    float4 u = p0[i], w = p1[i];
    o[i] = make_float4(u.x + w.x, u.y + w.y, u.z + w.z, u.w + w.w);
}

// ---------------- launch ----------------
extern "C" void kernel_launch(void* const* d_in, const int* in_sizes, int n_in,
                              void* d_out, int out_size)
{
    const float* x      = (const float*)d_in[0];
    const float* gate_v = (const float*)d_in[1];
    const float* gate_g = (const float*)d_in[2];
    const float* gate_b = (const float*)d_in[3];
    const float* w1_v   = (const float*)d_in[4];
    const float* w1_g   = (const float*)d_in[5];
    const float* b1     = (const float*)d_in[6];
    const float* w2_v   = (const float*)d_in[7];
    const float* w2_g   = (const float*)d_in[8];
    const float* b2     = (const float*)d_in[9];
    float* out = (float*)d_out;

    cudaFuncSetAttribute(gemm_kernel<D_, true>,  cudaFuncAttributeMaxDynamicSharedMemorySize, SMEM_DYN);
    cudaFuncSetAttribute(gemm_kernel<H_, false>, cudaFuncAttributeMaxDynamicSharedMemorySize, SMEM_DYN);

    zero_counts_kernel<<<1, 32>>>();
    gate_norm_kernel<<<1, 256>>>(gate_v, gate_g);
    route_kernel<<<T_ / 8, 256>>>(x, gate_v, gate_b);
    gather_kernel<<<T_, 256>>>(x);
    wconv_kernel<<<(E_ * H_) / 8, 256>>>(w1_v, w1_g, 0, D_);
    wconv_kernel<<<(E_ * D_) / 8, 256>>>(w2_v, w2_g, 1, H_);

    gemm_kernel<D_, true><<<dim3(H_ / BN, T_ / BM, E_), NT, SMEM_DYN>>>(b1);
    gemm_kernel<H_, false><<<dim3(D_ / BN, T_ / BM, E_), NT, SMEM_DYN>>>(b2);

    sum_kernel<<<T_, 256>>>(out);
}